// round 1
// baseline (speedup 1.0000x reference)
#include <cuda_runtime.h>
#include <cstdint>

#define BB   32
#define TT   1024
#define HID  512
#define G4   2048            // 4*HID
#define MROWS (BB*TT)        // 32768
#define NCTA 128
#define OUT_MAIN (BB*TT*HID) // 16777216

// -------------------- device scratch (no cudaMalloc allowed) --------------------
__device__ float g_G[(size_t)MROWS * G4];          // 256 MB: precomputed input-side gates
__device__ float g_Y0[(size_t)(TT + 1) * BB * HID]; // layer-0 hidden outputs (slot t+1 = h_t)
__device__ unsigned g_bar[2];

// -------------------- init: zero barriers --------------------
__global__ void init_kernel() {
    if (threadIdx.x < 2) g_bar[threadIdx.x] = 0u;
}

// -------------------- big GEMM: G[r][c] = sum_k A[r][k]*W[c][k] + bih[c]+bhh[c] ----
// MODE 0: A row r maps to input[b][t][:], r = t*32+b  (input is [B,T,I])
// MODE 1: A row r maps to Aptr + r*HID (contiguous rows)
template <int MODE>
__global__ __launch_bounds__(256) void gemm_kernel(
    const float* __restrict__ A,
    const float* __restrict__ W,      // [2048][512]
    const float* __restrict__ bih,    // [2048]
    const float* __restrict__ bhh,    // [2048]
    float* __restrict__ Gout)         // [32768][2048]
{
    __shared__ float As[128 * 17];
    __shared__ float Bs[64 * 17];

    const int tid = threadIdx.x;
    const int bm = blockIdx.y;        // 0..255
    const int bn = blockIdx.x;        // 0..31
    const int ty = tid >> 4;          // 0..15
    const int tx = tid & 15;          // 0..15
    const int m0 = ty * 8;
    const int n0 = tx * 4;

    float acc[8][4];
#pragma unroll
    for (int i = 0; i < 8; i++)
#pragma unroll
        for (int j = 0; j < 4; j++) acc[i][j] = 0.f;

    for (int kt = 0; kt < HID; kt += 16) {
        // load A tile: 128 rows x 16 k
#pragma unroll
        for (int q = 0; q < 2; q++) {
            int idx = tid + q * 256;           // 0..511
            int lrow = idx >> 2;               // 0..127
            int lk = (idx & 3) << 2;           // 0,4,8,12
            int r = bm * 128 + lrow;
            const float* ap;
            if (MODE == 0)
                ap = A + ((size_t)(r & 31) * TT + (size_t)(r >> 5)) * HID;
            else
                ap = A + (size_t)r * HID;
            float4 v = *(const float4*)(ap + kt + lk);
            float* d = &As[lrow * 17 + lk];
            d[0] = v.x; d[1] = v.y; d[2] = v.z; d[3] = v.w;
        }
        // load B tile: 64 rows x 16 k
        {
            int ln = tid >> 2;                 // 0..63
            int lk = (tid & 3) << 2;
            float4 v = *(const float4*)(W + (size_t)(bn * 64 + ln) * HID + kt + lk);
            float* d = &Bs[ln * 17 + lk];
            d[0] = v.x; d[1] = v.y; d[2] = v.z; d[3] = v.w;
        }
        __syncthreads();

#pragma unroll
        for (int k = 0; k < 16; k++) {
            float a[8], b[4];
#pragma unroll
            for (int i = 0; i < 8; i++) a[i] = As[(m0 + i) * 17 + k];
#pragma unroll
            for (int j = 0; j < 4; j++) b[j] = Bs[(n0 + j) * 17 + k];
#pragma unroll
            for (int i = 0; i < 8; i++)
#pragma unroll
                for (int j = 0; j < 4; j++) acc[i][j] += a[i] * b[j];
        }
        __syncthreads();
    }

    // epilogue: add bias, store
#pragma unroll
    for (int j = 0; j < 4; j++) {
        int col = bn * 64 + n0 + j;
        float bias = bih[col] + bhh[col];
#pragma unroll
        for (int i = 0; i < 8; i++) {
            int r = bm * 128 + m0 + i;
            Gout[(size_t)r * G4 + col] = acc[i][j] + bias;
        }
    }
}

// -------------------- persistent recurrence kernel --------------------
// 128 CTAs, 1/SM. CTA owns 4 hidden units j0..j0+3 -> 16 gate rows
// (g = type*4 + u, global gate col = type*512 + j0 + u).
// Per step: gates = G[t] + h_{t-1} @ Whh^T ; activations ; c,h update.
__global__ __launch_bounds__(256, 1) void recur_kernel(
    int layer,
    const float* __restrict__ Whh,   // this layer: [2048][512]
    const float* __restrict__ h0l,   // this layer: [32][512]
    const float* __restrict__ c0l,   // this layer: [32][512]
    float* __restrict__ out)         // d_out base
{
    extern __shared__ float sm[];
    float* h_s     = sm;                       // 32 * 517
    float* w_s     = h_s + 32 * 517;           // 512 * 20
    float* red     = w_s + 512 * 20;           // 512 * 8
    float* gates_s = red + 512 * 8;            // 512
    float* c_s     = gates_s + 512;            // 128

    const int tid = threadIdx.x;
    const int cta = blockIdx.x;
    const int j0 = cta * 4;

    // ---- load Whh slice (transposed: w_s[k*20 + g]) ----
    {
        int g = tid >> 4;                      // 0..15
        int type = g >> 2, u = g & 3;
        const float* wr = Whh + (size_t)(type * HID + j0 + u) * HID;
        int k0 = (tid & 15) * 32;
#pragma unroll 8
        for (int kk = 0; kk < 32; kk++)
            w_s[(k0 + kk) * 20 + g] = wr[k0 + kk];
    }
    // ---- init resident cell state ----
    if (tid < 128) {
        int b = tid & 31, u = tid >> 5;
        c_s[u * 32 + b] = c0l[(size_t)b * HID + j0 + u];
    }
    __syncthreads();

    const int kpos = tid >> 5;                 // 0..7
    const int sub = tid & 31;
    const int gpos = sub >> 3;                 // 0..3
    const int bpos = sub & 7;                  // 0..7
    const int g0 = gpos * 4;
    const int b0 = bpos * 4;
    const int kbase = kpos * 64;

    const int o0 = tid, o1 = tid + 256;        // outputs handled in reduce phase
    const int ga0 = o0 >> 5, ba0 = o0 & 31;
    const int ga1 = o1 >> 5, ba1 = o1 & 31;
    const size_t gcol0 = (size_t)(ga0 >> 2) * HID + j0 + (ga0 & 3);
    const size_t gcol1 = (size_t)(ga1 >> 2) * HID + j0 + (ga1 & 3);

    float* out_h_sec = out + OUT_MAIN;
    float* out_c_sec = out + OUT_MAIN + 2 * BB * HID;

    for (int t = 0; t < TT; t++) {
        // ---- stage h_{t-1} into smem ----
        const float* src;
        size_t rstride;
        if (layer == 0) {
            src = (t == 0) ? h0l : (g_Y0 + (size_t)t * BB * HID);
            rstride = HID;
        } else {
            if (t == 0) { src = h0l; rstride = HID; }
            else { src = out + (size_t)(t - 1) * HID; rstride = (size_t)TT * HID; }
        }
#pragma unroll
        for (int q = 0; q < 16; q++) {
            int idx = q * 256 + tid;           // 0..4095 float4s
            int b = idx >> 7;
            int jj = (idx & 127) << 2;
            float4 v = *(const float4*)(src + (size_t)b * rstride + jj);
            float* d = &h_s[b * 517 + jj];
            d[0] = v.x; d[1] = v.y; d[2] = v.z; d[3] = v.w;
        }
        // prefetch this step's precomputed input-side gates (hidden under mainloop)
        float Gv0 = g_G[(size_t)(t * BB + ba0) * G4 + gcol0];
        float Gv1 = g_G[(size_t)(t * BB + ba1) * G4 + gcol1];
        __syncthreads();

        // ---- recurrent GEMM slice: acc[b 4][g 4] over k in [kbase, kbase+64) ----
        float acc[4][4];
#pragma unroll
        for (int i = 0; i < 4; i++)
#pragma unroll
            for (int j = 0; j < 4; j++) acc[i][j] = 0.f;

#pragma unroll 8
        for (int kk = 0; kk < 64; kk++) {
            int k = kbase + kk;
            float4 w = *(const float4*)&w_s[k * 20 + g0];
            float hv0 = h_s[(b0 + 0) * 517 + k];
            float hv1 = h_s[(b0 + 1) * 517 + k];
            float hv2 = h_s[(b0 + 2) * 517 + k];
            float hv3 = h_s[(b0 + 3) * 517 + k];
            acc[0][0] += hv0 * w.x; acc[0][1] += hv0 * w.y; acc[0][2] += hv0 * w.z; acc[0][3] += hv0 * w.w;
            acc[1][0] += hv1 * w.x; acc[1][1] += hv1 * w.y; acc[1][2] += hv1 * w.z; acc[1][3] += hv1 * w.w;
            acc[2][0] += hv2 * w.x; acc[2][1] += hv2 * w.y; acc[2][2] += hv2 * w.z; acc[2][3] += hv2 * w.w;
            acc[3][0] += hv3 * w.x; acc[3][1] += hv3 * w.y; acc[3][2] += hv3 * w.z; acc[3][3] += hv3 * w.w;
        }

        // ---- write k-split partials ----
#pragma unroll
        for (int j = 0; j < 4; j++)
#pragma unroll
            for (int i = 0; i < 4; i++)
                red[((g0 + j) * 32 + (b0 + i)) * 8 + kpos] = acc[i][j];
        __syncthreads();

        // ---- reduce partials + add input-side gates ----
        {
            float4 r0 = *(const float4*)&red[o0 * 8];
            float4 r1 = *(const float4*)&red[o0 * 8 + 4];
            gates_s[o0] = Gv0 + ((r0.x + r0.y) + (r0.z + r0.w)) + ((r1.x + r1.y) + (r1.z + r1.w));
            float4 s0 = *(const float4*)&red[o1 * 8];
            float4 s1 = *(const float4*)&red[o1 * 8 + 4];
            gates_s[o1] = Gv1 + ((s0.x + s0.y) + (s0.z + s0.w)) + ((s1.x + s1.y) + (s1.z + s1.w));
        }
        __syncthreads();

        // ---- activations + state update + h broadcast write ----
        if (tid < 128) {
            int b = tid & 31, u = tid >> 5;
            float xi = gates_s[(0 + u) * 32 + b];
            float xf = gates_s[(4 + u) * 32 + b];
            float xg = gates_s[(8 + u) * 32 + b];
            float xo = gates_s[(12 + u) * 32 + b];
            float iv = 1.f / (1.f + __expf(-xi));
            float fv = 1.f / (1.f + __expf(-xf));
            float gv = tanhf(xg);
            float ov = 1.f / (1.f + __expf(-xo));
            float c = fv * c_s[u * 32 + b] + iv * gv;
            c_s[u * 32 + b] = c;
            float h = ov * tanhf(c);
            if (layer == 0) {
                g_Y0[(size_t)((t + 1) * BB + b) * HID + j0 + u] = h;
            } else {
                out[((size_t)b * TT + t) * HID + j0 + u] = h;
            }
            if (t == TT - 1) {
                out_h_sec[(size_t)(layer * BB + b) * HID + j0 + u] = h;
                out_c_sec[(size_t)(layer * BB + b) * HID + j0 + u] = c;
            }
        }

        // ---- global barrier (counter-only, monotonic, zeroed by init each launch) ----
        __syncthreads();
        if (tid == 0) {
            __threadfence();
            atomicAdd(&g_bar[layer], 1u);
            unsigned target = (unsigned)(t + 1) * NCTA;
            unsigned v;
            do {
                asm volatile("ld.acquire.gpu.b32 %0, [%1];" : "=r"(v) : "l"(&g_bar[layer]) : "memory");
                if (v >= target) break;
                __nanosleep(32);
            } while (true);
            __threadfence();
        }
        __syncthreads();
    }
}

// -------------------- launch --------------------
extern "C" void kernel_launch(void* const* d_in, const int* in_sizes, int n_in,
                              void* d_out, int out_size) {
    const float* input = (const float*)d_in[0];   // [32,1024,512]
    const float* h0    = (const float*)d_in[1];   // [2,32,512]
    const float* c0    = (const float*)d_in[2];   // [2,32,512]
    const float* W_ih  = (const float*)d_in[3];   // [2,2048,512]
    const float* W_hh  = (const float*)d_in[4];   // [2,2048,512]
    const float* b_ih  = (const float*)d_in[5];   // [2,2048]
    const float* b_hh  = (const float*)d_in[6];   // [2,2048]
    float* out = (float*)d_out;

    const int smem_recur = (32 * 517 + 512 * 20 + 512 * 8 + 512 + 128) * 4; // 126080 B
    cudaFuncSetAttribute(recur_kernel, cudaFuncAttributeMaxDynamicSharedMemorySize, smem_recur);

    float* Gptr;
    cudaGetSymbolAddress((void**)&Gptr, g_G);
    float* Y0ptr;
    cudaGetSymbolAddress((void**)&Y0ptr, g_Y0);

    init_kernel<<<1, 32>>>();

    dim3 ggrid(32, 256);

    // Layer 0: input-side gates, then recurrence
    gemm_kernel<0><<<ggrid, 256>>>(input, W_ih, b_ih, b_hh, Gptr);
    recur_kernel<<<NCTA, 256, smem_recur>>>(0, W_hh, h0, c0, out);

    // Layer 1: input = layer-0 outputs (Y0 slots 1..1024 are contiguous rows r+32)
    gemm_kernel<1><<<ggrid, 256>>>(Y0ptr + BB * HID, W_ih + (size_t)G4 * HID,
                                   b_ih + G4, b_hh + G4, Gptr);
    recur_kernel<<<NCTA, 256, smem_recur>>>(1, W_hh + (size_t)G4 * HID,
                                            h0 + BB * HID, c0 + BB * HID, out);
}

// round 3
// speedup vs baseline: 1.0237x; 1.0237x over previous
#include <cuda_runtime.h>
#include <cstdint>

#define BB   32
#define TT   1024
#define HID  512
#define G4   2048            // 4*HID
#define MROWS (BB*TT)        // 32768
#define NCTA 128
#define OUT_MAIN (BB*TT*HID) // 16777216

typedef unsigned long long ull;

__device__ __forceinline__ ull pack2(float x) {
    ull d; asm("mov.b64 %0, {%1, %1};" : "=l"(d) : "f"(x)); return d;
}
__device__ __forceinline__ ull fma2(ull a, ull b, ull c) {
    ull d; asm("fma.rn.f32x2 %0, %1, %2, %3;" : "=l"(d) : "l"(a), "l"(b), "l"(c)); return d;
}
__device__ __forceinline__ void unpack2(ull v, float& lo, float& hi) {
    asm("mov.b64 {%0, %1}, %2;" : "=f"(lo), "=f"(hi) : "l"(v));
}

// -------------------- device scratch (no cudaMalloc allowed) --------------------
__device__ float g_G[(size_t)MROWS * G4];           // 256 MB: precomputed input-side gates
__device__ float g_Y0[(size_t)(TT + 1) * BB * HID]; // layer-0 hidden outputs (slot t+1 = h_t)
__device__ unsigned g_bar[2];

// -------------------- init: zero barriers --------------------
__global__ void init_kernel() {
    if (threadIdx.x < 2) g_bar[threadIdx.x] = 0u;
}

// -------------------- big GEMM (FFMA2): G[r][c] = sum_k A[r][k]*W[c][k] + bias ----
// MODE 0: A row r maps to input[b][t][:], r = t*32+b  (input is [B,T,I])
// MODE 1: A row r maps to A + r*HID (contiguous rows)
// Tiles: 128m x 64n x 16k. Smem stored TRANSPOSED: As[k][m] (stride 132),
// Bs[k][n] (stride 66). Thread tile: m in {4ty..4ty+3, 64+4ty..64+4ty+3},
// n pairs {2tx,2tx+1} and {32+2tx,33+2tx} -> f32x2 accumulators.
template <int MODE>
__global__ __launch_bounds__(256) void gemm_kernel(
    const float* __restrict__ A,
    const float* __restrict__ W,      // [2048][512]
    const float* __restrict__ bih,    // [2048]
    const float* __restrict__ bhh,    // [2048]
    float* __restrict__ Gout)         // [32768][2048]
{
    __shared__ float As[16 * 132];
    __shared__ float Bs[16 * 66];

    const int tid = threadIdx.x;
    const int bm = blockIdx.y;        // 0..255
    const int bn = blockIdx.x;        // 0..31
    const int ty = tid >> 4;          // 0..15
    const int tx = tid & 15;          // 0..15

    ull acc2[8][2];
#pragma unroll
    for (int i = 0; i < 8; i++) { acc2[i][0] = 0ULL; acc2[i][1] = 0ULL; }

    for (int kt = 0; kt < HID; kt += 16) {
        // ---- stage A tile transposed: As[k][m] ----
#pragma unroll
        for (int q = 0; q < 2; q++) {
            int idx = tid + q * 256;           // 0..511
            int lrow = idx >> 2;               // m: 0..127
            int lk = (idx & 3) << 2;           // 0,4,8,12
            int r = bm * 128 + lrow;
            const float* ap;
            if (MODE == 0)
                ap = A + ((size_t)(r & 31) * TT + (size_t)(r >> 5)) * HID;
            else
                ap = A + (size_t)r * HID;
            float4 v = *(const float4*)(ap + kt + lk);
            As[(lk + 0) * 132 + lrow] = v.x;
            As[(lk + 1) * 132 + lrow] = v.y;
            As[(lk + 2) * 132 + lrow] = v.z;
            As[(lk + 3) * 132 + lrow] = v.w;
        }
        // ---- stage B tile transposed: Bs[k][n] ----
        {
            int ln = tid >> 2;                 // n: 0..63
            int lk = (tid & 3) << 2;
            float4 v = *(const float4*)(W + (size_t)(bn * 64 + ln) * HID + kt + lk);
            Bs[(lk + 0) * 66 + ln] = v.x;
            Bs[(lk + 1) * 66 + ln] = v.y;
            Bs[(lk + 2) * 66 + ln] = v.z;
            Bs[(lk + 3) * 66 + ln] = v.w;
        }
        __syncthreads();

#pragma unroll
        for (int k = 0; k < 16; k++) {
            float4 a0 = *(const float4*)&As[k * 132 + 4 * ty];
            float4 a1 = *(const float4*)&As[k * 132 + 64 + 4 * ty];
            ull bp0 = *(const ull*)&Bs[k * 66 + 2 * tx];
            ull bp1 = *(const ull*)&Bs[k * 66 + 32 + 2 * tx];
            float av[8] = {a0.x, a0.y, a0.z, a0.w, a1.x, a1.y, a1.z, a1.w};
#pragma unroll
            for (int i = 0; i < 8; i++) {
                ull ad = pack2(av[i]);
                acc2[i][0] = fma2(ad, bp0, acc2[i][0]);
                acc2[i][1] = fma2(ad, bp1, acc2[i][1]);
            }
        }
        __syncthreads();
    }

    // ---- epilogue: add bias, store as float2 pairs ----
    int c0 = bn * 64 + 2 * tx;        // pair c0, c0+1
    int c1 = c0 + 32;                 // pair c1, c1+1
    float bias00 = bih[c0] + bhh[c0];
    float bias01 = bih[c0 + 1] + bhh[c0 + 1];
    float bias10 = bih[c1] + bhh[c1];
    float bias11 = bih[c1 + 1] + bhh[c1 + 1];
#pragma unroll
    for (int i = 0; i < 8; i++) {
        int m = (i < 4) ? (4 * ty + i) : (64 + 4 * ty + i - 4);
        size_t r = (size_t)(bm * 128 + m);
        float x, y;
        unpack2(acc2[i][0], x, y);
        *(float2*)(Gout + r * G4 + c0) = make_float2(x + bias00, y + bias01);
        unpack2(acc2[i][1], x, y);
        *(float2*)(Gout + r * G4 + c1) = make_float2(x + bias10, y + bias11);
    }
}

// -------------------- persistent recurrence kernel (FFMA2 inner loop) ----------
// 128 CTAs, 1/SM. CTA owns 4 hidden units j0..j0+3 -> 16 gate rows.
__global__ __launch_bounds__(256, 1) void recur_kernel(
    int layer,
    const float* __restrict__ Whh,   // this layer: [2048][512]
    const float* __restrict__ h0l,   // this layer: [32][512]
    const float* __restrict__ c0l,   // this layer: [32][512]
    float* __restrict__ out)         // d_out base
{
    extern __shared__ float sm[];
    float* h_s     = sm;                       // 32 * 517
    float* w_s     = h_s + 32 * 517;           // 512 * 20
    float* red     = w_s + 512 * 20;           // 512 * 8
    float* gates_s = red + 512 * 8;            // 512
    float* c_s     = gates_s + 512;            // 128

    const int tid = threadIdx.x;
    const int cta = blockIdx.x;
    const int j0 = cta * 4;

    // ---- load Whh slice (transposed: w_s[k*20 + g]) ----
    {
        int g = tid >> 4;                      // 0..15
        int type = g >> 2, u = g & 3;
        const float* wr = Whh + (size_t)(type * HID + j0 + u) * HID;
        int k0 = (tid & 15) * 32;
#pragma unroll 8
        for (int kk = 0; kk < 32; kk++)
            w_s[(k0 + kk) * 20 + g] = wr[k0 + kk];
    }
    // ---- init resident cell state ----
    if (tid < 128) {
        int b = tid & 31, u = tid >> 5;
        c_s[u * 32 + b] = c0l[(size_t)b * HID + j0 + u];
    }
    __syncthreads();

    const int kpos = tid >> 5;                 // 0..7 (warp id)
    const int sub = tid & 31;
    const int gpos = sub >> 3;                 // 0..3
    const int bpos = sub & 7;                  // 0..7
    const int g0 = gpos * 4;
    const int b0 = bpos * 4;
    const int kbase = kpos * 64;

    const int o0 = tid, o1 = tid + 256;
    const int ga0 = o0 >> 5, ba0 = o0 & 31;
    const int ga1 = o1 >> 5, ba1 = o1 & 31;
    const size_t gcol0 = (size_t)(ga0 >> 2) * HID + j0 + (ga0 & 3);
    const size_t gcol1 = (size_t)(ga1 >> 2) * HID + j0 + (ga1 & 3);

    float* out_h_sec = out + OUT_MAIN;
    float* out_c_sec = out + OUT_MAIN + 2 * BB * HID;

    for (int t = 0; t < TT; t++) {
        // ---- stage h_{t-1} into smem ----
        const float* src;
        size_t rstride;
        if (layer == 0) {
            src = (t == 0) ? h0l : (g_Y0 + (size_t)t * BB * HID);
            rstride = HID;
        } else {
            if (t == 0) { src = h0l; rstride = HID; }
            else { src = out + (size_t)(t - 1) * HID; rstride = (size_t)TT * HID; }
        }
#pragma unroll
        for (int q = 0; q < 16; q++) {
            int idx = q * 256 + tid;           // 0..4095 float4s
            int b = idx >> 7;
            int jj = (idx & 127) << 2;
            float4 v = *(const float4*)(src + (size_t)b * rstride + jj);
            float* d = &h_s[b * 517 + jj];
            d[0] = v.x; d[1] = v.y; d[2] = v.z; d[3] = v.w;
        }
        // prefetch this step's precomputed input-side gates
        float Gv0 = g_G[(size_t)(t * BB + ba0) * G4 + gcol0];
        float Gv1 = g_G[(size_t)(t * BB + ba1) * G4 + gcol1];
        __syncthreads();

        // ---- recurrent GEMM slice, f32x2 packed:
        // accA[i] = gates (g0,g0+1), accB[i] = (g0+2,g0+3) for batch b0+i
        ull accA[4], accB[4];
#pragma unroll
        for (int i = 0; i < 4; i++) { accA[i] = 0ULL; accB[i] = 0ULL; }

#pragma unroll 8
        for (int kk = 0; kk < 64; kk++) {
            int k = kbase + kk;
            ull wA = *(const ull*)&w_s[k * 20 + g0];
            ull wB = *(const ull*)&w_s[k * 20 + g0 + 2];
#pragma unroll
            for (int i = 0; i < 4; i++) {
                ull hd = pack2(h_s[(b0 + i) * 517 + k]);
                accA[i] = fma2(hd, wA, accA[i]);
                accB[i] = fma2(hd, wB, accB[i]);
            }
        }

        // ---- write k-split partials ----
#pragma unroll
        for (int i = 0; i < 4; i++) {
            float v0, v1, v2, v3;
            unpack2(accA[i], v0, v1);
            unpack2(accB[i], v2, v3);
            red[((g0 + 0) * 32 + (b0 + i)) * 8 + kpos] = v0;
            red[((g0 + 1) * 32 + (b0 + i)) * 8 + kpos] = v1;
            red[((g0 + 2) * 32 + (b0 + i)) * 8 + kpos] = v2;
            red[((g0 + 3) * 32 + (b0 + i)) * 8 + kpos] = v3;
        }
        __syncthreads();

        // ---- reduce partials + add input-side gates ----
        {
            float4 r0 = *(const float4*)&red[o0 * 8];
            float4 r1 = *(const float4*)&red[o0 * 8 + 4];
            gates_s[o0] = Gv0 + ((r0.x + r0.y) + (r0.z + r0.w)) + ((r1.x + r1.y) + (r1.z + r1.w));
            float4 s0 = *(const float4*)&red[o1 * 8];
            float4 s1 = *(const float4*)&red[o1 * 8 + 4];
            gates_s[o1] = Gv1 + ((s0.x + s0.y) + (s0.z + s0.w)) + ((s1.x + s1.y) + (s1.z + s1.w));
        }
        __syncthreads();

        // ---- activations + state update + h write ----
        if (tid < 128) {
            int b = tid & 31, u = tid >> 5;
            float xi = gates_s[(0 + u) * 32 + b];
            float xf = gates_s[(4 + u) * 32 + b];
            float xg = gates_s[(8 + u) * 32 + b];
            float xo = gates_s[(12 + u) * 32 + b];
            float iv = 1.f / (1.f + __expf(-xi));
            float fv = 1.f / (1.f + __expf(-xf));
            float gv = tanhf(xg);
            float ov = 1.f / (1.f + __expf(-xo));
            float c = fv * c_s[u * 32 + b] + iv * gv;
            c_s[u * 32 + b] = c;
            float h = ov * tanhf(c);
            if (layer == 0) {
                g_Y0[(size_t)((t + 1) * BB + b) * HID + j0 + u] = h;
            } else {
                out[((size_t)b * TT + t) * HID + j0 + u] = h;
            }
            if (t == TT - 1) {
                out_h_sec[(size_t)(layer * BB + b) * HID + j0 + u] = h;
                out_c_sec[(size_t)(layer * BB + b) * HID + j0 + u] = c;
            }
        }

        // ---- global barrier (counter-only, monotonic) ----
        __syncthreads();
        if (tid == 0) {
            __threadfence();
            atomicAdd(&g_bar[layer], 1u);
            unsigned target = (unsigned)(t + 1) * NCTA;
            unsigned v;
            do {
                asm volatile("ld.acquire.gpu.b32 %0, [%1];" : "=r"(v) : "l"(&g_bar[layer]) : "memory");
                if (v >= target) break;
                __nanosleep(32);
            } while (true);
            __threadfence();
        }
        __syncthreads();
    }
}

// -------------------- launch --------------------
extern "C" void kernel_launch(void* const* d_in, const int* in_sizes, int n_in,
                              void* d_out, int out_size) {
    const float* input = (const float*)d_in[0];   // [32,1024,512]
    const float* h0    = (const float*)d_in[1];   // [2,32,512]
    const float* c0    = (const float*)d_in[2];   // [2,32,512]
    const float* W_ih  = (const float*)d_in[3];   // [2,2048,512]
    const float* W_hh  = (const float*)d_in[4];   // [2,2048,512]
    const float* b_ih  = (const float*)d_in[5];   // [2,2048]
    const float* b_hh  = (const float*)d_in[6];   // [2,2048]
    float* out = (float*)d_out;

    const int smem_recur = (32 * 517 + 512 * 20 + 512 * 8 + 512 + 128) * 4; // 126080 B
    cudaFuncSetAttribute(recur_kernel, cudaFuncAttributeMaxDynamicSharedMemorySize, smem_recur);

    float* Gptr;
    cudaGetSymbolAddress((void**)&Gptr, g_G);
    float* Y0ptr;
    cudaGetSymbolAddress((void**)&Y0ptr, g_Y0);

    init_kernel<<<1, 32>>>();

    dim3 ggrid(32, 256);

    // Layer 0
    gemm_kernel<0><<<ggrid, 256>>>(input, W_ih, b_ih, b_hh, Gptr);
    recur_kernel<<<NCTA, 256, smem_recur>>>(0, W_hh, h0, c0, out);

    // Layer 1: input = layer-0 outputs (Y0 slots 1..1024 are contiguous rows r+32)
    gemm_kernel<1><<<ggrid, 256>>>(Y0ptr + BB * HID, W_ih + (size_t)G4 * HID,
                                   b_ih + G4, b_hh + G4, Gptr);
    recur_kernel<<<NCTA, 256, smem_recur>>>(1, W_hh + (size_t)G4 * HID,
                                            h0 + BB * HID, c0 + BB * HID, out);
}